// round 4
// baseline (speedup 1.0000x reference)
#include <cuda_runtime.h>
#include <cuda_bf16.h>

// MyLoss: masked per-class MSE, fused single kernel.
// Output (21 fp32): [0]=loss, [1..10]=loss4each, [11..20]=class_n
//
// Key structure: per-class partial sums live in TWO disjoint class-major smem
// arrays (A: components x,z; B: components y,w) so the compiler can overlap the
// otherwise-serialized LDS->FADD->STS read-modify-write chains. Counts are
// accumulated in packed per-thread registers (6 bits/class, max 32/thread).
// Occupancy 8 (31-32 regs) is load-bearing: it is what hides the smem RAW chain.

#define N_CLASSES 10
#define THREADS   256
#define NBLOCKS   1024
#define ITERS     8     // 1024*256*8 = 2,097,152 = nvec exactly

__device__ float        g_sum[N_CLASSES];
__device__ float        g_cnt[N_CLASSES];
__device__ unsigned int g_done = 0;

// int (0..9) -> float without I2F (IADD + FADD, both lat-4 pipes)
__device__ __forceinline__ float small_i2f(int t) {
    return __int_as_float(0x4B000000 + t) - 8388608.0f;
}

__global__ void __launch_bounds__(THREADS, 8)
myloss_fused_kernel(const float4* __restrict__ outv,
                    const int4*   __restrict__ tgtv,
                    const int4*   __restrict__ mskv,
                    int nvec,
                    float* __restrict__ out) {
    // Class-major: s[c*THREADS + tid]; lane L always hits bank L%32 -> no conflicts.
    __shared__ float s_sumA[N_CLASSES * THREADS];  // x,z components
    __shared__ float s_sumB[N_CLASSES * THREADS];  // y,w components
    __shared__ bool  s_is_last;

    const int tid = threadIdx.x;
    #pragma unroll
    for (int c = 0; c < N_CLASSES; ++c) {
        s_sumA[c * THREADS + tid] = 0.0f;
        s_sumB[c * THREADS + tid] = 0.0f;
    }
    __syncthreads();

    // Packed per-thread counters: 6 bits/class (max 32 masked pixels/thread).
    unsigned int cnt_lo = 0u;   // classes 0..4
    unsigned int cnt_hi = 0u;   // classes 5..9

#define PROC(ARR, O, T, M)                                                   \
    do {                                                                     \
        if ((M) == 1) {                                                      \
            float d = (O) - small_i2f(T);                                    \
            ARR[(T) * THREADS + tid] += d * d;                               \
            if ((T) < 5) cnt_lo += 1u << (6 * (T));                          \
            else         cnt_hi += 1u << (6 * ((T) - 5));                    \
        }                                                                    \
    } while (0)

    const int stride = NBLOCKS * THREADS;
    if (nvec == NBLOCKS * THREADS * ITERS) {
        int i = blockIdx.x * THREADS + tid;
        #pragma unroll
        for (int k = 0; k < ITERS; ++k, i += stride) {
            const float4 o = outv[i];
            const int4   t = tgtv[i];
            const int4   m = mskv[i];
            PROC(s_sumA, o.x, t.x, m.x);
            PROC(s_sumB, o.y, t.y, m.y);
            PROC(s_sumA, o.z, t.z, m.z);
            PROC(s_sumB, o.w, t.w, m.w);
        }
    } else {
        for (int i = blockIdx.x * THREADS + tid; i < nvec; i += stride) {
            const float4 o = outv[i];
            const int4   t = tgtv[i];
            const int4   m = mskv[i];
            PROC(s_sumA, o.x, t.x, m.x);
            PROC(s_sumB, o.y, t.y, m.y);
            PROC(s_sumA, o.z, t.z, m.z);
            PROC(s_sumB, o.w, t.w, m.w);
        }
    }
#undef PROC

    __syncthreads();

    // Epilogue: 20 reduce-jobs (10 sums = A+B, 10 counts from packed regs).
    // First spill packed counters into s_sumA's tail? No -- reuse registers:
    // counts: each warp reduces its own lanes' packed fields via shuffles, then
    // per-class totals via one pass. Simpler: unpack into s_sumB after merging
    // A into B? Need both. Do: merge A+=B per class first, then reuse s_sumB
    // for counts.
    const int wid  = tid >> 5;
    const int lane = tid & 31;

    // Merge B into A (conflict-free, fully parallel).
    #pragma unroll
    for (int c = 0; c < N_CLASSES; ++c)
        s_sumA[c * THREADS + tid] += s_sumB[c * THREADS + tid];
    __syncthreads();   // not strictly needed before unpack (disjoint), kept for clarity

    // Unpack counters into s_sumB (same layout).
    #pragma unroll
    for (int c = 0; c < 5; ++c) {
        s_sumB[c * THREADS + tid]       = (float)((cnt_lo >> (6 * c)) & 63u);
        s_sumB[(c + 5) * THREADS + tid] = (float)((cnt_hi >> (6 * c)) & 63u);
    }
    __syncthreads();

    // 20 jobs over 8 warps: each warp reduces a full 256-wide class column.
    for (int j = wid; j < 2 * N_CLASSES; j += THREADS / 32) {
        const float* base = (j < N_CLASSES) ? &s_sumA[j * THREADS]
                                            : &s_sumB[(j - N_CLASSES) * THREADS];
        float v = 0.0f;
        #pragma unroll
        for (int k = 0; k < THREADS / 32; ++k)
            v += base[k * 32 + lane];
        #pragma unroll
        for (int off = 16; off > 0; off >>= 1)
            v += __shfl_down_sync(0xFFFFFFFFu, v, off);
        if (lane == 0) {
            if (j < N_CLASSES) atomicAdd(&g_sum[j], v);
            else               atomicAdd(&g_cnt[j - N_CLASSES], v);
        }
    }

    // Last-block election.
    if (tid == 0) {
        __threadfence();
        unsigned int ticket = atomicAdd(&g_done, 1u);
        s_is_last = (ticket == gridDim.x - 1);
    }
    __syncthreads();

    if (s_is_last && tid < 32) {
        float l = 0.0f, n = 0.0f;
        if (tid < N_CLASSES) {
            float s = atomicAdd(&g_sum[tid], 0.0f);  // RMW read: latest value
            n       = atomicAdd(&g_cnt[tid], 0.0f);
            l = (n > 0.0f) ? (s / fmaxf(n, 1.0f)) : 0.0f;
            out[1 + tid]             = l;
            out[1 + N_CLASSES + tid] = n;
            g_sum[tid] = 0.0f;                       // reset for next graph replay
            g_cnt[tid] = 0.0f;
        }
        float w = (tid < N_CLASSES) ? 0.1f * l : 0.0f;
        #pragma unroll
        for (int off = 16; off > 0; off >>= 1)
            w += __shfl_down_sync(0xFFFFFFFFu, w, off);
        if (tid == 0) {
            out[0] = w;
            g_done = 0u;
        }
    }
}

extern "C" void kernel_launch(void* const* d_in, const int* in_sizes, int n_in,
                              void* d_out, int out_size) {
    const float* outputs = (const float*)d_in[0];
    const int*   targets = (const int*)d_in[1];
    const int*   mask    = (const int*)d_in[2];
    float*       out     = (float*)d_out;

    const int n    = in_sizes[0];   // 8,388,608
    const int nvec = n / 4;

    myloss_fused_kernel<<<NBLOCKS, THREADS>>>(
        (const float4*)outputs, (const int4*)targets, (const int4*)mask,
        nvec, out);
}